// round 15
// baseline (speedup 1.0000x reference)
#include <cuda_runtime.h>
#include <cuda_fp16.h>

#define N_NODES 100000
#define N_EDGES_MAX 1600000
#define D 128
#define ND (N_NODES * D)
#define GROWS 64
#define NTILE ((N_NODES + GROWS - 1) / GROWS)       // 1563
// gemm smem: Wq[128*128] + z[64*128] floats = 96KB
#define GEMM_SMEM_FLOATS (128*128 + GROWS*128)
#define GEMM_SMEM_BYTES (GEMM_SMEM_FLOATS * 4)

typedef unsigned long long ull;

__device__ float g_z[(size_t)(NTILE * GROWS) * D];
__device__ float g_y[ND];
__device__ __half g_h16[ND];        // fp16 mirror of current h for the gather path
__device__ float g_sA[3][2 * D];
__device__ float g_sB[3][2 * D];
__device__ int g_deg[N_NODES];      // zero at init; re-zeroed by scan_k after use
__device__ int g_off[N_NODES + 1];
__device__ int g_cur[N_NODES];
__device__ int g_eidx[N_EDGES_MAX];

__device__ __forceinline__ void ffma2(ull& d, ull a, ull b) {
    asm("fma.rn.f32x2 %0, %1, %2, %0;" : "+l"(d) : "l"(a), "l"(b));
}
__device__ __forceinline__ void unpk2(float& a, float& b, ull v) {
    asm("mov.b64 {%0, %1}, %2;" : "=f"(a), "=f"(b) : "l"(v));
}
__device__ __forceinline__ void cp16(void* smem_dst, const void* gmem_src) {
    unsigned s = (unsigned)__cvta_generic_to_shared(smem_dst);
    asm volatile("cp.async.cg.shared.global [%0], [%1], 16;" :: "r"(s), "l"(gmem_src));
}
__device__ __forceinline__ void cp_commit() { asm volatile("cp.async.commit_group;"); }
__device__ __forceinline__ void cp_wait0() { asm volatile("cp.async.wait_group 0;"); }

__device__ __forceinline__ uint2 pack16(float4 v) {
    __half2 a = __floats2half2_rn(v.x, v.y);
    __half2 b = __floats2half2_rn(v.z, v.w);
    uint2 u;
    u.x = *(unsigned*)&a;
    u.y = *(unsigned*)&b;
    return u;
}
__device__ __forceinline__ uint2 hadd2_u2(uint2 a, uint2 b) {
    __half2 x = __hadd2(*(__half2*)&a.x, *(__half2*)&b.x);
    __half2 y = __hadd2(*(__half2*)&a.y, *(__half2*)&b.y);
    uint2 r;
    r.x = *(unsigned*)&x;
    r.y = *(unsigned*)&y;
    return r;
}
__device__ __forceinline__ void accu2(float4& acc, uint2 u) {
    float2 f0 = __half22float2(*(__half2*)&u.x);
    float2 f1 = __half22float2(*(__half2*)&u.y);
    acc.x += f0.x; acc.y += f0.y; acc.z += f1.x; acc.w += f1.y;
}

__device__ __forceinline__ void bn_consts(const float* st, const float* gamma,
                                          const float* beta, int c0,
                                          float4& sc, float4& sh) {
    float4 sum = *(const float4*)&st[c0];
    float4 sq  = *(const float4*)&st[128 + c0];
    float4 ga  = *(const float4*)&gamma[c0];
    float4 be  = *(const float4*)&beta[c0];
    const float inv = 1.0f / N_NODES;
    float m, v;
    m = sum.x * inv; v = sq.x * inv - m * m; sc.x = rsqrtf(v + 1e-5f) * ga.x; sh.x = be.x - m * sc.x;
    m = sum.y * inv; v = sq.y * inv - m * m; sc.y = rsqrtf(v + 1e-5f) * ga.y; sh.y = be.y - m * sc.y;
    m = sum.z * inv; v = sq.z * inv - m * m; sc.z = rsqrtf(v + 1e-5f) * ga.z; sh.z = be.z - m * sc.z;
    m = sum.w * inv; v = sq.w * inv - m * m; sc.w = rsqrtf(v + 1e-5f) * ga.w; sh.w = be.w - m * sc.w;
}

// ---------------- launch 1: copy features (+fp16 mirror) + zero stats ----------------
__global__ void copyzero_k(float* __restrict__ out, const float* __restrict__ features) {
    int gt = blockIdx.x * blockDim.x + threadIdx.x;
    int stride = gridDim.x * blockDim.x;
    const float4* f4 = (const float4*)features;
    float4* o4 = (float4*)out;
    uint2* h16 = (uint2*)g_h16;
    for (int i = gt; i < ND / 4; i += stride) {
        float4 v = f4[i];
        o4[i] = v;
        h16[i] = pack16(v);
    }
    if (gt < 3 * 2 * D) {
        ((float*)g_sA)[gt] = 0.f;
        ((float*)g_sB)[gt] = 0.f;
    }
}

// ---------------- launch 2: degree histogram ----------------
__global__ void hist_k(const int* __restrict__ dst, int nE) {
    for (int e = blockIdx.x * blockDim.x + threadIdx.x; e < nE; e += gridDim.x * blockDim.x)
        atomicAdd(&g_deg[dst[e]], 1);
}

// ---------------- launch 3: scan (consumes g_deg and re-zeroes it) ----------------
__global__ void scan_k(int nE) {
    __shared__ int sm[1024];
    const int t = threadIdx.x;
    const int CH = (N_NODES + 1023) / 1024;
    int base = t * CH;
    int s = 0;
    for (int i = 0; i < CH; i++) {
        int idx = base + i;
        if (idx < N_NODES) s += g_deg[idx];
    }
    sm[t] = s;
    __syncthreads();
    for (int d = 1; d < 1024; d <<= 1) {
        int v = (t >= d) ? sm[t - d] : 0;
        __syncthreads();
        sm[t] += v;
        __syncthreads();
    }
    int off = sm[t] - s;
    for (int i = 0; i < CH; i++) {
        int idx = base + i;
        if (idx < N_NODES) {
            int dg = g_deg[idx];
            g_off[idx] = off;
            g_cur[idx] = off;
            off += dg;
            g_deg[idx] = 0;   // replay-invariant
        }
    }
    if (t == 1023) g_off[N_NODES] = nE;
}

// ---------------- launch 4: fill CSR ----------------
__global__ void fill_k(const int* __restrict__ src, const int* __restrict__ dst, int nE) {
    for (int e = blockIdx.x * blockDim.x + threadIdx.x; e < nE; e += gridDim.x * blockDim.x) {
        int p = atomicAdd(&g_cur[dst[e]], 1);
        g_eidx[p] = src[e];
    }
}

// ---------------- gather, warp-per-row, fp16 reads + HADD2 pairing ----------------
__global__ void __launch_bounds__(256, 6)
gather_k(const float* __restrict__ h, const float* __restrict__ eps, int layer) {
    const int lane = threadIdx.x & 31;
    const int gw = (blockIdx.x * blockDim.x + threadIdx.x) >> 5;
    const int nw = (gridDim.x * blockDim.x) >> 5;
    const float e1 = 1.0f + __ldg(&eps[layer]);
    const float4* hp = (const float4*)h;
    const uint2* h16 = (const uint2*)g_h16;
    float4* zp4 = (float4*)g_z;

    for (int row = gw; row < N_NODES; row += nw) {
        int start = g_off[row];
        int deg = g_off[row + 1] - start;
        float4 v = hp[(size_t)row * 32 + lane];
        float4 acc;
        acc.x = e1 * v.x; acc.y = e1 * v.y; acc.z = e1 * v.z; acc.w = e1 * v.w;
        for (int basee = 0; basee < deg; basee += 32) {
            int m = deg - basee; if (m > 32) m = 32;
            int idx = 0;
            if (lane < m) idx = g_eidx[start + basee + lane];
            int l = 0;
            for (; l + 8 <= m; l += 8) {
                int s0 = __shfl_sync(0xffffffffu, idx, l);
                int s1 = __shfl_sync(0xffffffffu, idx, l + 1);
                int s2 = __shfl_sync(0xffffffffu, idx, l + 2);
                int s3 = __shfl_sync(0xffffffffu, idx, l + 3);
                int s4 = __shfl_sync(0xffffffffu, idx, l + 4);
                int s5 = __shfl_sync(0xffffffffu, idx, l + 5);
                int s6 = __shfl_sync(0xffffffffu, idx, l + 6);
                int s7 = __shfl_sync(0xffffffffu, idx, l + 7);
                uint2 u0 = h16[(size_t)s0 * 32 + lane];
                uint2 u1 = h16[(size_t)s1 * 32 + lane];
                uint2 u2 = h16[(size_t)s2 * 32 + lane];
                uint2 u3 = h16[(size_t)s3 * 32 + lane];
                uint2 u4 = h16[(size_t)s4 * 32 + lane];
                uint2 u5 = h16[(size_t)s5 * 32 + lane];
                uint2 u6 = h16[(size_t)s6 * 32 + lane];
                uint2 u7 = h16[(size_t)s7 * 32 + lane];
                accu2(acc, hadd2_u2(u0, u1));
                accu2(acc, hadd2_u2(u2, u3));
                accu2(acc, hadd2_u2(u4, u5));
                accu2(acc, hadd2_u2(u6, u7));
            }
            for (; l + 2 <= m; l += 2) {
                int s0 = __shfl_sync(0xffffffffu, idx, l);
                int s1 = __shfl_sync(0xffffffffu, idx, l + 1);
                uint2 u0 = h16[(size_t)s0 * 32 + lane];
                uint2 u1 = h16[(size_t)s1 * 32 + lane];
                accu2(acc, hadd2_u2(u0, u1));
            }
            for (; l < m; l++) {
                int s0 = __shfl_sync(0xffffffffu, idx, l);
                accu2(acc, h16[(size_t)s0 * 32 + lane]);
            }
        }
        zp4[(size_t)row * 32 + lane] = acc;
    }
}

// ---------------- GEMM + BN1 stats: 2 blocks/SM, 64-row tiles, cross-block overlap ----------------
__global__ void __launch_bounds__(256, 2)
gemm_stats_k(const float* __restrict__ W, const float* __restrict__ b, int layer) {
    extern __shared__ float sm[];
    float* Wq = sm;                 // 16384 floats, k-pair interleaved
    float* zs = sm + 128 * 128;     // 8192 floats (64 rows)
    float* rs = zs;                 // aliased after tile loop

    const int tid = threadIdx.x;
    const int warp = tid >> 5, lane = tid & 31;

    // load W: Wq[(k>>1)*256 + 2*c + (k&1)] = W[k][c]
    {
        const float4* W4 = (const float4*)W;
        #pragma unroll 4
        for (int i = tid; i < 128 * 128 / 4; i += 256) {
            int k = i >> 5;
            int c = (i & 31) * 4;
            float4 v = W4[i];
            float* base = &Wq[(k >> 1) * 256 + (k & 1)];
            base[2 * c + 0] = v.x;
            base[2 * c + 2] = v.y;
            base[2 * c + 4] = v.z;
            base[2 * c + 6] = v.w;
        }
    }

    const int c0 = lane, c1 = lane + 32, c2 = lane + 64, c3 = lane + 96;
    float bb0 = b[c0], bb1 = b[c1], bb2 = b[c2], bb3 = b[c3];
    float s0 = 0.f, s1 = 0.f, s2 = 0.f, s3 = 0.f;
    float q0 = 0.f, q1 = 0.f, q2 = 0.f, q3 = 0.f;
    __syncthreads();   // W visible

    for (int t = blockIdx.x; t < NTILE; t += gridDim.x) {
        // load 32KB z tile (2048 x 16B; 8 per thread)
        const char* src = (const char*)(g_z + (size_t)t * GROWS * 128);
        #pragma unroll
        for (int j = 0; j < 8; j++)
            cp16((char*)zs + (j * 256 + tid) * 16, src + (j * 256 + tid) * 16);
        cp_commit();
        cp_wait0();
        __syncthreads();

        ull acc[8][4];
        #pragma unroll
        for (int r = 0; r < 8; r++)
            #pragma unroll
            for (int j = 0; j < 4; j++) acc[r][j] = 0ull;

        #pragma unroll 2
        for (int k = 0; k < 128; k += 4) {
            int k2 = k >> 1;
            ull wa0 = *(ull*)&Wq[(k2 + 0) * 256 + 2 * c0];
            ull wa1 = *(ull*)&Wq[(k2 + 0) * 256 + 2 * c1];
            ull wa2 = *(ull*)&Wq[(k2 + 0) * 256 + 2 * c2];
            ull wa3 = *(ull*)&Wq[(k2 + 0) * 256 + 2 * c3];
            ull wb0 = *(ull*)&Wq[(k2 + 1) * 256 + 2 * c0];
            ull wb1 = *(ull*)&Wq[(k2 + 1) * 256 + 2 * c1];
            ull wb2 = *(ull*)&Wq[(k2 + 1) * 256 + 2 * c2];
            ull wb3 = *(ull*)&Wq[(k2 + 1) * 256 + 2 * c3];
            #pragma unroll
            for (int r = 0; r < 8; r++) {
                ulonglong2 zp = *(ulonglong2*)&zs[(warp * 8 + r) * 128 + k];
                ffma2(acc[r][0], zp.x, wa0);
                ffma2(acc[r][1], zp.x, wa1);
                ffma2(acc[r][2], zp.x, wa2);
                ffma2(acc[r][3], zp.x, wa3);
                ffma2(acc[r][0], zp.y, wb0);
                ffma2(acc[r][1], zp.y, wb1);
                ffma2(acc[r][2], zp.y, wb2);
                ffma2(acc[r][3], zp.y, wb3);
            }
        }

        #pragma unroll
        for (int r = 0; r < 8; r++) {
            int row = t * GROWS + warp * 8 + r;
            if (row < N_NODES) {
                float lo, hi, v0, v1, v2, v3;
                unpk2(lo, hi, acc[r][0]); v0 = lo + hi + bb0;
                unpk2(lo, hi, acc[r][1]); v1 = lo + hi + bb1;
                unpk2(lo, hi, acc[r][2]); v2 = lo + hi + bb2;
                unpk2(lo, hi, acc[r][3]); v3 = lo + hi + bb3;
                float* yr = g_y + (size_t)row * 128;
                yr[c0] = v0; yr[c1] = v1; yr[c2] = v2; yr[c3] = v3;
                s0 += v0; s1 += v1; s2 += v2; s3 += v3;
                q0 += v0 * v0; q1 += v1 * v1; q2 += v2 * v2; q3 += v3 * v3;
            }
        }
        __syncthreads();   // zs reusable next tile
    }

    // reduce BN1 stats (rs aliases zs)
    rs[warp * 128 + c0] = s0; rs[warp * 128 + c1] = s1;
    rs[warp * 128 + c2] = s2; rs[warp * 128 + c3] = s3;
    rs[1024 + warp * 128 + c0] = q0; rs[1024 + warp * 128 + c1] = q1;
    rs[1024 + warp * 128 + c2] = q2; rs[1024 + warp * 128 + c3] = q3;
    __syncthreads();
    int col = tid & 127;
    int so = (tid >> 7) * 1024;
    float v = 0.f;
    #pragma unroll
    for (int w = 0; w < 8; w++) v += rs[so + w * 128 + col];
    atomicAdd(&g_sA[layer][(tid >> 7) * 128 + col], v);
}

// read-only on g_y: apply BN1+ReLU on the fly, accumulate BN2 stats
__global__ void bn_relu_stats_k(const float* __restrict__ gamma1, const float* __restrict__ beta1,
                                int layer) {
    __shared__ float rs[2048];
    int tid = threadIdx.x, lane = tid & 31, warp = tid >> 5;
    int c0 = lane * 4;
    float4 sc, sh;
    bn_consts(g_sA[layer], gamma1, beta1, c0, sc, sh);
    float4 s = make_float4(0.f, 0.f, 0.f, 0.f);
    float4 q = make_float4(0.f, 0.f, 0.f, 0.f);
    const float4* y4 = (const float4*)g_y;
    int n4 = ND / 4;
    for (int i = blockIdx.x * 256 + tid; i < n4; i += gridDim.x * 256) {
        float4 v = y4[i];
        v.x = fmaxf(fmaf(v.x, sc.x, sh.x), 0.f);
        v.y = fmaxf(fmaf(v.y, sc.y, sh.y), 0.f);
        v.z = fmaxf(fmaf(v.z, sc.z, sh.z), 0.f);
        v.w = fmaxf(fmaf(v.w, sc.w, sh.w), 0.f);
        s.x += v.x; s.y += v.y; s.z += v.z; s.w += v.w;
        q.x += v.x * v.x; q.y += v.y * v.y; q.z += v.z * v.z; q.w += v.w * v.w;
    }
    rs[warp * 128 + c0 + 0] = s.x; rs[warp * 128 + c0 + 1] = s.y;
    rs[warp * 128 + c0 + 2] = s.z; rs[warp * 128 + c0 + 3] = s.w;
    rs[1024 + warp * 128 + c0 + 0] = q.x; rs[1024 + warp * 128 + c0 + 1] = q.y;
    rs[1024 + warp * 128 + c0 + 2] = q.z; rs[1024 + warp * 128 + c0 + 3] = q.w;
    __syncthreads();
    int col = tid & 127;
    int so = (tid >> 7) * 1024;
    float v = 0.f;
    #pragma unroll
    for (int w = 0; w < 8; w++) v += rs[so + w * 128 + col];
    atomicAdd(&g_sB[layer][(tid >> 7) * 128 + col], v);
}

// out = relu(bn2(relu(bn1(y)))) -> fp32 slab + fp16 mirror
__global__ void bn_relu_out_k(float* __restrict__ out,
                              const float* __restrict__ gamma1, const float* __restrict__ beta1,
                              const float* __restrict__ gamma2, const float* __restrict__ beta2,
                              int layer) {
    int tid = threadIdx.x, lane = tid & 31;
    int c0 = lane * 4;
    float4 sc1, sh1, sc2, sh2;
    bn_consts(g_sA[layer], gamma1, beta1, c0, sc1, sh1);
    bn_consts(g_sB[layer], gamma2, beta2, c0, sc2, sh2);
    const float4* y4 = (const float4*)g_y;
    float4* o4 = (float4*)out;
    uint2* h16 = (uint2*)g_h16;
    int n4 = ND / 4;
    for (int i = blockIdx.x * 256 + tid; i < n4; i += gridDim.x * 256) {
        float4 v = y4[i];
        v.x = fmaxf(fmaf(v.x, sc1.x, sh1.x), 0.f);
        v.y = fmaxf(fmaf(v.y, sc1.y, sh1.y), 0.f);
        v.z = fmaxf(fmaf(v.z, sc1.z, sh1.z), 0.f);
        v.w = fmaxf(fmaf(v.w, sc1.w, sh1.w), 0.f);
        v.x = fmaxf(fmaf(v.x, sc2.x, sh2.x), 0.f);
        v.y = fmaxf(fmaf(v.y, sc2.y, sh2.y), 0.f);
        v.z = fmaxf(fmaf(v.z, sc2.z, sh2.z), 0.f);
        v.w = fmaxf(fmaf(v.w, sc2.w, sh2.w), 0.f);
        o4[i] = v;
        h16[i] = pack16(v);
    }
}

extern "C" void kernel_launch(void* const* d_in, const int* in_sizes, int n_in,
                              void* d_out, int out_size) {
    const float* features = (const float*)d_in[0];
    const float* W   = (const float*)d_in[1];
    const float* b   = (const float*)d_in[2];
    const float* eps = (const float*)d_in[3];
    const float* g1  = (const float*)d_in[4];
    const float* be1 = (const float*)d_in[5];
    const float* g2  = (const float*)d_in[6];
    const float* be2 = (const float*)d_in[7];
    const int* src   = (const int*)d_in[8];
    const int* dst   = (const int*)d_in[9];
    int nE = in_sizes[8];
    float* out = (float*)d_out;

    static bool once = []() {
        cudaFuncSetAttribute(gemm_stats_k, cudaFuncAttributeMaxDynamicSharedMemorySize,
                             GEMM_SMEM_BYTES);
        return true;
    }();
    (void)once;

    copyzero_k<<<1184, 256>>>(out, features);
    hist_k<<<6250, 256>>>(dst, nE);
    scan_k<<<1, 1024>>>(nE);
    fill_k<<<6250, 256>>>(src, dst, nE);

    for (int i = 0; i < 3; i++) {
        const float* h = out + (size_t)i * ND;
        float* hn = out + (size_t)(i + 1) * ND;
        gather_k<<<1250, 256>>>(h, eps, i);
        gemm_stats_k<<<296, 256, GEMM_SMEM_BYTES>>>(W + (size_t)i * D * D, b + (size_t)i * D, i);
        bn_relu_stats_k<<<1184, 256>>>(g1 + i * D, be1 + i * D, i);
        bn_relu_out_k<<<1184, 256>>>(hn, g1 + i * D, be1 + i * D, g2 + i * D, be2 + i * D, i);
    }
}

// round 16
// speedup vs baseline: 1.0396x; 1.0396x over previous
#include <cuda_runtime.h>
#include <cuda_fp16.h>

#define N_NODES 100000
#define N_EDGES_MAX 1600000
#define D 128
#define ND (N_NODES * D)
#define GROWS 128
#define NTILE ((N_NODES + GROWS - 1) / GROWS)       // 782
#define NPAD (NTILE * GROWS)
#define GEMM_SMEM_FLOATS (128*128 + 2*GROWS*128)
#define GEMM_SMEM_BYTES (GEMM_SMEM_FLOATS * 4)

typedef unsigned long long ull;

__device__ float g_z[(size_t)NPAD * D];
__device__ float g_y[ND];
__device__ __half g_h16[ND];        // fp16 mirror of current h for the gather path
__device__ float g_sA[3][2 * D];
__device__ float g_sB[3][2 * D];
__device__ int g_deg[N_NODES];
__device__ int g_off[N_NODES + 1];
__device__ int g_cur[N_NODES];
__device__ int g_eidx[N_EDGES_MAX];

__device__ __forceinline__ void ffma2(ull& d, ull a, ull b) {
    asm("fma.rn.f32x2 %0, %1, %2, %0;" : "+l"(d) : "l"(a), "l"(b));
}
__device__ __forceinline__ void unpk2(float& a, float& b, ull v) {
    asm("mov.b64 {%0, %1}, %2;" : "=f"(a), "=f"(b) : "l"(v));
}
__device__ __forceinline__ void cp16(void* smem_dst, const void* gmem_src) {
    unsigned s = (unsigned)__cvta_generic_to_shared(smem_dst);
    asm volatile("cp.async.cg.shared.global [%0], [%1], 16;" :: "r"(s), "l"(gmem_src));
}
__device__ __forceinline__ void cp_commit() { asm volatile("cp.async.commit_group;"); }
__device__ __forceinline__ void cp_wait1() { asm volatile("cp.async.wait_group 1;"); }

__device__ __forceinline__ uint2 pack16(float4 v) {
    __half2 a = __floats2half2_rn(v.x, v.y);
    __half2 b = __floats2half2_rn(v.z, v.w);
    uint2 u;
    u.x = *(unsigned*)&a;
    u.y = *(unsigned*)&b;
    return u;
}
__device__ __forceinline__ uint2 hadd2_u2(uint2 a, uint2 b) {
    __half2 x = __hadd2(*(__half2*)&a.x, *(__half2*)&b.x);
    __half2 y = __hadd2(*(__half2*)&a.y, *(__half2*)&b.y);
    uint2 r;
    r.x = *(unsigned*)&x;
    r.y = *(unsigned*)&y;
    return r;
}
__device__ __forceinline__ void accu2(float4& acc, uint2 u) {
    float2 f0 = __half22float2(*(__half2*)&u.x);
    float2 f1 = __half22float2(*(__half2*)&u.y);
    acc.x += f0.x; acc.y += f0.y; acc.z += f1.x; acc.w += f1.y;
}

__device__ __forceinline__ void bn_consts(const float* st, const float* gamma,
                                          const float* beta, int c0,
                                          float4& sc, float4& sh) {
    float4 sum = *(const float4*)&st[c0];
    float4 sq  = *(const float4*)&st[128 + c0];
    float4 ga  = *(const float4*)&gamma[c0];
    float4 be  = *(const float4*)&beta[c0];
    const float inv = 1.0f / N_NODES;
    float m, v;
    m = sum.x * inv; v = sq.x * inv - m * m; sc.x = rsqrtf(v + 1e-5f) * ga.x; sh.x = be.x - m * sc.x;
    m = sum.y * inv; v = sq.y * inv - m * m; sc.y = rsqrtf(v + 1e-5f) * ga.y; sh.y = be.y - m * sc.y;
    m = sum.z * inv; v = sq.z * inv - m * m; sc.z = rsqrtf(v + 1e-5f) * ga.z; sh.z = be.z - m * sc.z;
    m = sum.w * inv; v = sq.w * inv - m * m; sc.w = rsqrtf(v + 1e-5f) * ga.w; sh.w = be.w - m * sc.w;
}

// ---------------- launch-start: copy features (+fp16 mirror), zero deg + stats ----------------
__global__ void copyzero_k(float* __restrict__ out, const float* __restrict__ features) {
    int gt = blockIdx.x * blockDim.x + threadIdx.x;
    int stride = gridDim.x * blockDim.x;
    const float4* f4 = (const float4*)features;
    float4* o4 = (float4*)out;
    uint2* h16 = (uint2*)g_h16;
    for (int i = gt; i < ND / 4; i += stride) {
        float4 v = f4[i];
        o4[i] = v;
        h16[i] = pack16(v);
    }
    for (int i = gt; i < N_NODES; i += stride) g_deg[i] = 0;
    if (gt < 3 * 2 * D) {
        ((float*)g_sA)[gt] = 0.f;
        ((float*)g_sB)[gt] = 0.f;
    }
}

// ---------------- CSR build ----------------
__global__ void hist_k(const int* __restrict__ dst, int nE) {
    for (int e = blockIdx.x * blockDim.x + threadIdx.x; e < nE; e += gridDim.x * blockDim.x)
        atomicAdd(&g_deg[dst[e]], 1);
}

__global__ void scan_k(int nE) {
    __shared__ int sm[1024];
    const int t = threadIdx.x;
    const int CH = (N_NODES + 1023) / 1024;
    int base = t * CH;
    int s = 0;
    for (int i = 0; i < CH; i++) {
        int idx = base + i;
        if (idx < N_NODES) s += g_deg[idx];
    }
    sm[t] = s;
    __syncthreads();
    for (int d = 1; d < 1024; d <<= 1) {
        int v = (t >= d) ? sm[t - d] : 0;
        __syncthreads();
        sm[t] += v;
        __syncthreads();
    }
    int off = sm[t] - s;
    for (int i = 0; i < CH; i++) {
        int idx = base + i;
        if (idx < N_NODES) {
            g_off[idx] = off;
            g_cur[idx] = off;
            off += g_deg[idx];
        }
    }
    if (t == 1023) g_off[N_NODES] = nE;
}

__global__ void fill_k(const int* __restrict__ src, const int* __restrict__ dst, int nE) {
    for (int e = blockIdx.x * blockDim.x + threadIdx.x; e < nE; e += gridDim.x * blockDim.x) {
        int p = atomicAdd(&g_cur[dst[e]], 1);
        g_eidx[p] = src[e];
    }
}

// ---------------- gather: warp-per-row, fp16 uint2 reads + HADD2 pairing ----------------
__global__ void __launch_bounds__(256, 6)
gather_k(const float* __restrict__ h, const float* __restrict__ eps, int layer) {
    const int lane = threadIdx.x & 31;
    const int gw = (blockIdx.x * blockDim.x + threadIdx.x) >> 5;
    const int nw = (gridDim.x * blockDim.x) >> 5;
    const float e1 = 1.0f + __ldg(&eps[layer]);
    const float4* hp = (const float4*)h;
    const uint2* h16 = (const uint2*)g_h16;
    float4* zp4 = (float4*)g_z;

    for (int row = gw; row < N_NODES; row += nw) {
        int start = g_off[row];
        int deg = g_off[row + 1] - start;
        float4 v = hp[(size_t)row * 32 + lane];
        float4 acc;
        acc.x = e1 * v.x; acc.y = e1 * v.y; acc.z = e1 * v.z; acc.w = e1 * v.w;
        for (int basee = 0; basee < deg; basee += 32) {
            int m = deg - basee; if (m > 32) m = 32;
            int idx = 0;
            if (lane < m) idx = g_eidx[start + basee + lane];
            int l = 0;
            for (; l + 8 <= m; l += 8) {
                int s0 = __shfl_sync(0xffffffffu, idx, l);
                int s1 = __shfl_sync(0xffffffffu, idx, l + 1);
                int s2 = __shfl_sync(0xffffffffu, idx, l + 2);
                int s3 = __shfl_sync(0xffffffffu, idx, l + 3);
                int s4 = __shfl_sync(0xffffffffu, idx, l + 4);
                int s5 = __shfl_sync(0xffffffffu, idx, l + 5);
                int s6 = __shfl_sync(0xffffffffu, idx, l + 6);
                int s7 = __shfl_sync(0xffffffffu, idx, l + 7);
                uint2 u0 = h16[(size_t)s0 * 32 + lane];
                uint2 u1 = h16[(size_t)s1 * 32 + lane];
                uint2 u2 = h16[(size_t)s2 * 32 + lane];
                uint2 u3 = h16[(size_t)s3 * 32 + lane];
                uint2 u4 = h16[(size_t)s4 * 32 + lane];
                uint2 u5 = h16[(size_t)s5 * 32 + lane];
                uint2 u6 = h16[(size_t)s6 * 32 + lane];
                uint2 u7 = h16[(size_t)s7 * 32 + lane];
                accu2(acc, hadd2_u2(u0, u1));
                accu2(acc, hadd2_u2(u2, u3));
                accu2(acc, hadd2_u2(u4, u5));
                accu2(acc, hadd2_u2(u6, u7));
            }
            for (; l + 2 <= m; l += 2) {
                int s0 = __shfl_sync(0xffffffffu, idx, l);
                int s1 = __shfl_sync(0xffffffffu, idx, l + 1);
                uint2 u0 = h16[(size_t)s0 * 32 + lane];
                uint2 u1 = h16[(size_t)s1 * 32 + lane];
                accu2(acc, hadd2_u2(u0, u1));
            }
            for (; l < m; l++) {
                int s0 = __shfl_sync(0xffffffffu, idx, l);
                accu2(acc, h16[(size_t)s0 * 32 + lane]);
            }
        }
        zp4[(size_t)row * 32 + lane] = acc;
    }
}

// ---------------- persistent GEMM + BN1 stats (R12 exact) ----------------
__global__ void __launch_bounds__(512, 1)
gemm_stats_k(const float* __restrict__ W, const float* __restrict__ b, int layer) {
    extern __shared__ float sm[];
    float* Wq  = sm;
    float* zb0 = sm + 128 * 128;
    float* zb1 = zb0 + GROWS * 128;
    float* rs  = zb0;

    const int tid = threadIdx.x;
    const int warp = tid >> 5, lane = tid & 31;

    {
        const float4* W4 = (const float4*)W;
        #pragma unroll 2
        for (int i = tid; i < 128 * 128 / 4; i += 512) {
            int k = i >> 5;
            int c = (i & 31) * 4;
            float4 v = W4[i];
            float* base = &Wq[(k >> 1) * 256 + (k & 1)];
            base[2 * c + 0] = v.x;
            base[2 * c + 2] = v.y;
            base[2 * c + 4] = v.z;
            base[2 * c + 6] = v.w;
        }
    }

    const int c0 = lane, c1 = lane + 32, c2 = lane + 64, c3 = lane + 96;
    float bb0 = b[c0], bb1 = b[c1], bb2 = b[c2], bb3 = b[c3];
    float s0 = 0.f, s1 = 0.f, s2 = 0.f, s3 = 0.f;
    float q0 = 0.f, q1 = 0.f, q2 = 0.f, q3 = 0.f;

    const int t0 = blockIdx.x;
    if (t0 < NTILE) {
        const char* src = (const char*)(g_z + (size_t)t0 * GROWS * 128);
        #pragma unroll
        for (int j = 0; j < 8; j++)
            cp16((char*)zb0 + (j * 512 + tid) * 16, src + (j * 512 + tid) * 16);
    }
    cp_commit();
    __syncthreads();

    int i = 0;
    for (int t = t0; t < NTILE; t += gridDim.x, i++) {
        float* zs = (i & 1) ? zb1 : zb0;
        int tn = t + gridDim.x;
        if (tn < NTILE) {
            float* zn = (i & 1) ? zb0 : zb1;
            const char* src = (const char*)(g_z + (size_t)tn * GROWS * 128);
            #pragma unroll
            for (int j = 0; j < 8; j++)
                cp16((char*)zn + (j * 512 + tid) * 16, src + (j * 512 + tid) * 16);
        }
        cp_commit();
        cp_wait1();
        __syncthreads();

        ull acc[8][4];
        #pragma unroll
        for (int r = 0; r < 8; r++)
            #pragma unroll
            for (int j = 0; j < 4; j++) acc[r][j] = 0ull;

        #pragma unroll 2
        for (int k = 0; k < 128; k += 4) {
            int k2 = k >> 1;
            ull wa0 = *(ull*)&Wq[(k2 + 0) * 256 + 2 * c0];
            ull wa1 = *(ull*)&Wq[(k2 + 0) * 256 + 2 * c1];
            ull wa2 = *(ull*)&Wq[(k2 + 0) * 256 + 2 * c2];
            ull wa3 = *(ull*)&Wq[(k2 + 0) * 256 + 2 * c3];
            ull wb0 = *(ull*)&Wq[(k2 + 1) * 256 + 2 * c0];
            ull wb1 = *(ull*)&Wq[(k2 + 1) * 256 + 2 * c1];
            ull wb2 = *(ull*)&Wq[(k2 + 1) * 256 + 2 * c2];
            ull wb3 = *(ull*)&Wq[(k2 + 1) * 256 + 2 * c3];
            #pragma unroll
            for (int r = 0; r < 8; r++) {
                ulonglong2 zp = *(ulonglong2*)&zs[(warp * 8 + r) * 128 + k];
                ffma2(acc[r][0], zp.x, wa0);
                ffma2(acc[r][1], zp.x, wa1);
                ffma2(acc[r][2], zp.x, wa2);
                ffma2(acc[r][3], zp.x, wa3);
                ffma2(acc[r][0], zp.y, wb0);
                ffma2(acc[r][1], zp.y, wb1);
                ffma2(acc[r][2], zp.y, wb2);
                ffma2(acc[r][3], zp.y, wb3);
            }
        }

        #pragma unroll
        for (int r = 0; r < 8; r++) {
            int row = t * GROWS + warp * 8 + r;
            if (row < N_NODES) {
                float lo, hi, v0, v1, v2, v3;
                unpk2(lo, hi, acc[r][0]); v0 = lo + hi + bb0;
                unpk2(lo, hi, acc[r][1]); v1 = lo + hi + bb1;
                unpk2(lo, hi, acc[r][2]); v2 = lo + hi + bb2;
                unpk2(lo, hi, acc[r][3]); v3 = lo + hi + bb3;
                float* yr = g_y + (size_t)row * 128;
                yr[c0] = v0; yr[c1] = v1; yr[c2] = v2; yr[c3] = v3;
                s0 += v0; s1 += v1; s2 += v2; s3 += v3;
                q0 += v0 * v0; q1 += v1 * v1; q2 += v2 * v2; q3 += v3 * v3;
            }
        }
        __syncthreads();
    }

    __syncthreads();
    rs[warp * 128 + c0] = s0; rs[warp * 128 + c1] = s1;
    rs[warp * 128 + c2] = s2; rs[warp * 128 + c3] = s3;
    rs[2048 + warp * 128 + c0] = q0; rs[2048 + warp * 128 + c1] = q1;
    rs[2048 + warp * 128 + c2] = q2; rs[2048 + warp * 128 + c3] = q3;
    __syncthreads();
    if (tid < 256) {
        int col = tid & 127;
        int so = (tid >> 7) * 2048;
        float v = 0.f;
        #pragma unroll
        for (int w = 0; w < 16; w++) v += rs[so + w * 128 + col];
        atomicAdd(&g_sA[layer][(tid >> 7) * 128 + col], v);
    }
}

// read-only on g_y: apply BN1+ReLU on the fly, accumulate BN2 stats
__global__ void bn_relu_stats_k(const float* __restrict__ gamma1, const float* __restrict__ beta1,
                                int layer) {
    __shared__ float rs[2048];
    int tid = threadIdx.x, lane = tid & 31, warp = tid >> 5;
    int c0 = lane * 4;
    float4 sc, sh;
    bn_consts(g_sA[layer], gamma1, beta1, c0, sc, sh);
    float4 s = make_float4(0.f, 0.f, 0.f, 0.f);
    float4 q = make_float4(0.f, 0.f, 0.f, 0.f);
    const float4* y4 = (const float4*)g_y;
    int n4 = ND / 4;
    for (int i = blockIdx.x * 256 + tid; i < n4; i += gridDim.x * 256) {
        float4 v = y4[i];
        v.x = fmaxf(fmaf(v.x, sc.x, sh.x), 0.f);
        v.y = fmaxf(fmaf(v.y, sc.y, sh.y), 0.f);
        v.z = fmaxf(fmaf(v.z, sc.z, sh.z), 0.f);
        v.w = fmaxf(fmaf(v.w, sc.w, sh.w), 0.f);
        s.x += v.x; s.y += v.y; s.z += v.z; s.w += v.w;
        q.x += v.x * v.x; q.y += v.y * v.y; q.z += v.z * v.z; q.w += v.w * v.w;
    }
    rs[warp * 128 + c0 + 0] = s.x; rs[warp * 128 + c0 + 1] = s.y;
    rs[warp * 128 + c0 + 2] = s.z; rs[warp * 128 + c0 + 3] = s.w;
    rs[1024 + warp * 128 + c0 + 0] = q.x; rs[1024 + warp * 128 + c0 + 1] = q.y;
    rs[1024 + warp * 128 + c0 + 2] = q.z; rs[1024 + warp * 128 + c0 + 3] = q.w;
    __syncthreads();
    int col = tid & 127;
    int so = (tid >> 7) * 1024;
    float v = 0.f;
    #pragma unroll
    for (int w = 0; w < 8; w++) v += rs[so + w * 128 + col];
    atomicAdd(&g_sB[layer][(tid >> 7) * 128 + col], v);
}

// out = relu(bn2(relu(bn1(y)))) -> fp32 slab + fp16 mirror
__global__ void bn_relu_out_k(float* __restrict__ out,
                              const float* __restrict__ gamma1, const float* __restrict__ beta1,
                              const float* __restrict__ gamma2, const float* __restrict__ beta2,
                              int layer) {
    int tid = threadIdx.x, lane = tid & 31;
    int c0 = lane * 4;
    float4 sc1, sh1, sc2, sh2;
    bn_consts(g_sA[layer], gamma1, beta1, c0, sc1, sh1);
    bn_consts(g_sB[layer], gamma2, beta2, c0, sc2, sh2);
    const float4* y4 = (const float4*)g_y;
    float4* o4 = (float4*)out;
    uint2* h16 = (uint2*)g_h16;
    int n4 = ND / 4;
    for (int i = blockIdx.x * 256 + tid; i < n4; i += gridDim.x * 256) {
        float4 v = y4[i];
        v.x = fmaxf(fmaf(v.x, sc1.x, sh1.x), 0.f);
        v.y = fmaxf(fmaf(v.y, sc1.y, sh1.y), 0.f);
        v.z = fmaxf(fmaf(v.z, sc1.z, sh1.z), 0.f);
        v.w = fmaxf(fmaf(v.w, sc1.w, sh1.w), 0.f);
        v.x = fmaxf(fmaf(v.x, sc2.x, sh2.x), 0.f);
        v.y = fmaxf(fmaf(v.y, sc2.y, sh2.y), 0.f);
        v.z = fmaxf(fmaf(v.z, sc2.z, sh2.z), 0.f);
        v.w = fmaxf(fmaf(v.w, sc2.w, sh2.w), 0.f);
        o4[i] = v;
        h16[i] = pack16(v);
    }
}

extern "C" void kernel_launch(void* const* d_in, const int* in_sizes, int n_in,
                              void* d_out, int out_size) {
    const float* features = (const float*)d_in[0];
    const float* W   = (const float*)d_in[1];
    const float* b   = (const float*)d_in[2];
    const float* eps = (const float*)d_in[3];
    const float* g1  = (const float*)d_in[4];
    const float* be1 = (const float*)d_in[5];
    const float* g2  = (const float*)d_in[6];
    const float* be2 = (const float*)d_in[7];
    const int* src   = (const int*)d_in[8];
    const int* dst   = (const int*)d_in[9];
    int nE = in_sizes[8];
    float* out = (float*)d_out;

    static bool once = []() {
        cudaFuncSetAttribute(gemm_stats_k, cudaFuncAttributeMaxDynamicSharedMemorySize,
                             GEMM_SMEM_BYTES);
        return true;
    }();
    (void)once;

    copyzero_k<<<1184, 256>>>(out, features);
    hist_k<<<6250, 256>>>(dst, nE);
    scan_k<<<1, 1024>>>(nE);
    fill_k<<<6250, 256>>>(src, dst, nE);

    for (int i = 0; i < 3; i++) {
        const float* h = out + (size_t)i * ND;
        float* hn = out + (size_t)(i + 1) * ND;
        gather_k<<<1250, 256>>>(h, eps, i);
        gemm_stats_k<<<148, 512, GEMM_SMEM_BYTES>>>(W + (size_t)i * D * D, b + (size_t)i * D, i);
        bn_relu_stats_k<<<1184, 256>>>(g1 + i * D, be1 + i * D, i);
        bn_relu_out_k<<<1184, 256>>>(hn, g1 + i * D, be1 + i * D, g2 + i * D, be2 + i * D, i);
    }
}

// round 17
// speedup vs baseline: 1.3016x; 1.2521x over previous
#include <cuda_runtime.h>
#include <cuda_fp16.h>

#define N_NODES 100000
#define N_EDGES_MAX 1600000
#define D 128
#define ND (N_NODES * D)
#define GROWS 128
#define NTILE ((N_NODES + GROWS - 1) / GROWS)       // 782
#define NPAD (NTILE * GROWS)                         // 100096
// gemm smem: ws[128][136] + zs[128][136] halfs
#define MMA_SMEM_BYTES (2 * 128 * 136 * 2)

typedef unsigned long long ull;

__device__ float g_y[ND];
__device__ __half g_h16[ND];                 // fp16 mirror of current h (gather input)
__device__ __half g_z16[(size_t)NPAD * D];   // fp16 aggregation output (gemm input)
__device__ __half g_w16[3][D * D];           // fp16 weights
__device__ float g_sA[3][2 * D];
__device__ float g_sB[3][2 * D];
__device__ int g_deg[N_NODES];
__device__ int g_off[N_NODES + 1];
__device__ int g_cur[N_NODES];
__device__ int g_eidx[N_EDGES_MAX];

__device__ __forceinline__ void cp16(void* smem_dst, const void* gmem_src) {
    unsigned s = (unsigned)__cvta_generic_to_shared(smem_dst);
    asm volatile("cp.async.cg.shared.global [%0], [%1], 16;" :: "r"(s), "l"(gmem_src));
}
__device__ __forceinline__ void cp_commit() { asm volatile("cp.async.commit_group;"); }
__device__ __forceinline__ void cp_wait0() { asm volatile("cp.async.wait_group 0;"); }
__device__ __forceinline__ unsigned smem_u32(const void* p) {
    return (unsigned)__cvta_generic_to_shared(p);
}

__device__ __forceinline__ uint2 pack16(float4 v) {
    __half2 a = __floats2half2_rn(v.x, v.y);
    __half2 b = __floats2half2_rn(v.z, v.w);
    uint2 u;
    u.x = *(unsigned*)&a;
    u.y = *(unsigned*)&b;
    return u;
}
__device__ __forceinline__ uint2 hadd2_u2(uint2 a, uint2 b) {
    __half2 x = __hadd2(*(__half2*)&a.x, *(__half2*)&b.x);
    __half2 y = __hadd2(*(__half2*)&a.y, *(__half2*)&b.y);
    uint2 r;
    r.x = *(unsigned*)&x;
    r.y = *(unsigned*)&y;
    return r;
}
__device__ __forceinline__ void accu2(float4& acc, uint2 u) {
    float2 f0 = __half22float2(*(__half2*)&u.x);
    float2 f1 = __half22float2(*(__half2*)&u.y);
    acc.x += f0.x; acc.y += f0.y; acc.z += f1.x; acc.w += f1.y;
}

__device__ __forceinline__ void bn_consts(const float* st, const float* gamma,
                                          const float* beta, int c0,
                                          float4& sc, float4& sh) {
    float4 sum = *(const float4*)&st[c0];
    float4 sq  = *(const float4*)&st[128 + c0];
    float4 ga  = *(const float4*)&gamma[c0];
    float4 be  = *(const float4*)&beta[c0];
    const float inv = 1.0f / N_NODES;
    float m, v;
    m = sum.x * inv; v = sq.x * inv - m * m; sc.x = rsqrtf(v + 1e-5f) * ga.x; sh.x = be.x - m * sc.x;
    m = sum.y * inv; v = sq.y * inv - m * m; sc.y = rsqrtf(v + 1e-5f) * ga.y; sh.y = be.y - m * sc.y;
    m = sum.z * inv; v = sq.z * inv - m * m; sc.z = rsqrtf(v + 1e-5f) * ga.z; sh.z = be.z - m * sc.z;
    m = sum.w * inv; v = sq.w * inv - m * m; sc.w = rsqrtf(v + 1e-5f) * ga.w; sh.w = be.w - m * sc.w;
}

// ---------------- launch 1: copy features (+fp16 mirror), W->fp16, zero deg/stats ----------------
__global__ void copyzero_k(float* __restrict__ out, const float* __restrict__ features,
                           const float* __restrict__ W) {
    int gt = blockIdx.x * blockDim.x + threadIdx.x;
    int stride = gridDim.x * blockDim.x;
    const float4* f4 = (const float4*)features;
    float4* o4 = (float4*)out;
    uint2* h16 = (uint2*)g_h16;
    for (int i = gt; i < ND / 4; i += stride) {
        float4 v = f4[i];
        o4[i] = v;
        h16[i] = pack16(v);
    }
    for (int i = gt; i < N_NODES; i += stride) g_deg[i] = 0;
    for (int i = gt; i < 3 * D * D; i += stride)
        ((__half*)g_w16)[i] = __float2half(W[i]);
    if (gt < 3 * 2 * D) {
        ((float*)g_sA)[gt] = 0.f;
        ((float*)g_sB)[gt] = 0.f;
    }
}

// ---------------- CSR build ----------------
__global__ void hist_k(const int* __restrict__ dst, int nE) {
    for (int e = blockIdx.x * blockDim.x + threadIdx.x; e < nE; e += gridDim.x * blockDim.x)
        atomicAdd(&g_deg[dst[e]], 1);
}

__global__ void scan_k(int nE) {
    __shared__ int sm[1024];
    const int t = threadIdx.x;
    const int CH = (N_NODES + 1023) / 1024;
    int base = t * CH;
    int s = 0;
    for (int i = 0; i < CH; i++) {
        int idx = base + i;
        if (idx < N_NODES) s += g_deg[idx];
    }
    sm[t] = s;
    __syncthreads();
    for (int d = 1; d < 1024; d <<= 1) {
        int v = (t >= d) ? sm[t - d] : 0;
        __syncthreads();
        sm[t] += v;
        __syncthreads();
    }
    int off = sm[t] - s;
    for (int i = 0; i < CH; i++) {
        int idx = base + i;
        if (idx < N_NODES) {
            g_off[idx] = off;
            g_cur[idx] = off;
            off += g_deg[idx];
        }
    }
    if (t == 1023) g_off[N_NODES] = nE;
}

__global__ void fill_k(const int* __restrict__ src, const int* __restrict__ dst, int nE) {
    for (int e = blockIdx.x * blockDim.x + threadIdx.x; e < nE; e += gridDim.x * blockDim.x) {
        int p = atomicAdd(&g_cur[dst[e]], 1);
        g_eidx[p] = src[e];
    }
}

// ---------------- gather: warp-per-row, fp16 reads + HADD2 pairing, fp16 z out ----------------
__global__ void __launch_bounds__(256, 6)
gather_k(const float* __restrict__ h, const float* __restrict__ eps, int layer) {
    const int lane = threadIdx.x & 31;
    const int gw = (blockIdx.x * blockDim.x + threadIdx.x) >> 5;
    const int nw = (gridDim.x * blockDim.x) >> 5;
    const float e1 = 1.0f + __ldg(&eps[layer]);
    const float4* hp = (const float4*)h;
    const uint2* h16 = (const uint2*)g_h16;
    uint2* z16 = (uint2*)g_z16;

    for (int row = gw; row < N_NODES; row += nw) {
        int start = g_off[row];
        int deg = g_off[row + 1] - start;
        float4 v = hp[(size_t)row * 32 + lane];
        float4 acc;
        acc.x = e1 * v.x; acc.y = e1 * v.y; acc.z = e1 * v.z; acc.w = e1 * v.w;
        for (int basee = 0; basee < deg; basee += 32) {
            int m = deg - basee; if (m > 32) m = 32;
            int idx = 0;
            if (lane < m) idx = g_eidx[start + basee + lane];
            int l = 0;
            for (; l + 8 <= m; l += 8) {
                int s0 = __shfl_sync(0xffffffffu, idx, l);
                int s1 = __shfl_sync(0xffffffffu, idx, l + 1);
                int s2 = __shfl_sync(0xffffffffu, idx, l + 2);
                int s3 = __shfl_sync(0xffffffffu, idx, l + 3);
                int s4 = __shfl_sync(0xffffffffu, idx, l + 4);
                int s5 = __shfl_sync(0xffffffffu, idx, l + 5);
                int s6 = __shfl_sync(0xffffffffu, idx, l + 6);
                int s7 = __shfl_sync(0xffffffffu, idx, l + 7);
                uint2 u0 = h16[(size_t)s0 * 32 + lane];
                uint2 u1 = h16[(size_t)s1 * 32 + lane];
                uint2 u2 = h16[(size_t)s2 * 32 + lane];
                uint2 u3 = h16[(size_t)s3 * 32 + lane];
                uint2 u4 = h16[(size_t)s4 * 32 + lane];
                uint2 u5 = h16[(size_t)s5 * 32 + lane];
                uint2 u6 = h16[(size_t)s6 * 32 + lane];
                uint2 u7 = h16[(size_t)s7 * 32 + lane];
                accu2(acc, hadd2_u2(u0, u1));
                accu2(acc, hadd2_u2(u2, u3));
                accu2(acc, hadd2_u2(u4, u5));
                accu2(acc, hadd2_u2(u6, u7));
            }
            for (; l + 2 <= m; l += 2) {
                int s0 = __shfl_sync(0xffffffffu, idx, l);
                int s1 = __shfl_sync(0xffffffffu, idx, l + 1);
                uint2 u0 = h16[(size_t)s0 * 32 + lane];
                uint2 u1 = h16[(size_t)s1 * 32 + lane];
                accu2(acc, hadd2_u2(u0, u1));
            }
            for (; l < m; l++) {
                int s0 = __shfl_sync(0xffffffffu, idx, l);
                accu2(acc, h16[(size_t)s0 * 32 + lane]);
            }
        }
        z16[(size_t)row * 32 + lane] = pack16(acc);
    }
}

// ---------------- GEMM via mma.sync m16n8k16 (fp16 in, fp32 accum) ----------------
// block = 256 threads = 8 warps; warp computes 16 rows x 128 cols; block tile = 128 rows.
// smem: ws[128][136] halfs (W), zs[128][136] halfs (z tile); 272B row stride = conflict-free ldmatrix.
__global__ void __launch_bounds__(256)
gemm_mma_k(const float* __restrict__ b, int layer) {
    extern __shared__ __half sh[];
    __half* ws = sh;                 // 128*136
    __half* zs = sh + 128 * 136;

    const int tid = threadIdx.x;
    const int warp = tid >> 5, lane = tid & 31;
    const int row0 = blockIdx.x * GROWS;

    // async-load W16 and z16 tiles (2048 16B-chunks each, 8 per thread per array)
    const __half* wsrc = g_w16[layer];
    #pragma unroll
    for (int j = 0; j < 8; j++) {
        int ch = j * 256 + tid;
        int r = ch >> 4, c = ch & 15;
        cp16((char*)ws + r * 272 + c * 16, (const char*)wsrc + r * 256 + c * 16);
    }
    const __half* zsrc = g_z16 + (size_t)row0 * D;
    #pragma unroll
    for (int j = 0; j < 8; j++) {
        int ch = j * 256 + tid;
        int r = ch >> 4, c = ch & 15;
        cp16((char*)zs + r * 272 + c * 16, (const char*)zsrc + r * 256 + c * 16);
    }
    cp_commit();
    cp_wait0();
    __syncthreads();

    // ldmatrix source lanes: rows 0-7 -> mat0, 8-15 -> mat1, 16-23 -> mat2, 24-31 -> mat3
    const int lrow = (lane & 7) + ((lane >> 3) & 1) * 8;   // 0..15
    const int lcol8 = ((lane >> 4) & 1) * 8;               // 0 or 8
    unsigned abase = smem_u32(zs + (warp * 16 + lrow) * 136 + lcol8);
    unsigned bbase = smem_u32(ws + lrow * 136 + lcol8);

    float acc[16][4];
    #pragma unroll
    for (int n = 0; n < 16; n++) {
        acc[n][0] = acc[n][1] = acc[n][2] = acc[n][3] = 0.f;
    }

    #pragma unroll
    for (int kk = 0; kk < 8; kk++) {
        unsigned a0, a1, a2, a3;
        asm volatile("ldmatrix.sync.aligned.m8n8.x4.shared.b16 {%0,%1,%2,%3}, [%4];"
                     : "=r"(a0), "=r"(a1), "=r"(a2), "=r"(a3)
                     : "r"(abase + kk * 32));
        #pragma unroll
        for (int np = 0; np < 8; np++) {
            unsigned b0, b1, b2, b3;
            asm volatile("ldmatrix.sync.aligned.m8n8.x4.trans.shared.b16 {%0,%1,%2,%3}, [%4];"
                         : "=r"(b0), "=r"(b1), "=r"(b2), "=r"(b3)
                         : "r"(bbase + kk * 16 * 272 + np * 32));
            asm volatile("mma.sync.aligned.m16n8k16.row.col.f32.f16.f16.f32 "
                         "{%0,%1,%2,%3}, {%4,%5,%6,%7}, {%8,%9}, {%0,%1,%2,%3};"
                         : "+f"(acc[np * 2][0]), "+f"(acc[np * 2][1]),
                           "+f"(acc[np * 2][2]), "+f"(acc[np * 2][3])
                         : "r"(a0), "r"(a1), "r"(a2), "r"(a3), "r"(b0), "r"(b1));
            asm volatile("mma.sync.aligned.m16n8k16.row.col.f32.f16.f16.f32 "
                         "{%0,%1,%2,%3}, {%4,%5,%6,%7}, {%8,%9}, {%0,%1,%2,%3};"
                         : "+f"(acc[np * 2 + 1][0]), "+f"(acc[np * 2 + 1][1]),
                           "+f"(acc[np * 2 + 1][2]), "+f"(acc[np * 2 + 1][3])
                         : "r"(a0), "r"(a1), "r"(a2), "r"(a3), "r"(b2), "r"(b3));
        }
    }

    // epilogue: +bias, store fp32 y
    const int g = lane >> 2, tq = lane & 3;
    const int r1 = row0 + warp * 16 + g;
    const int r2 = r1 + 8;
    #pragma unroll
    for (int nt = 0; nt < 16; nt++) {
        int col = nt * 8 + tq * 2;
        float b0v = __ldg(&b[col]);
        float b1v = __ldg(&b[col + 1]);
        if (r1 < N_NODES) {
            float2 v;
            v.x = acc[nt][0] + b0v;
            v.y = acc[nt][1] + b1v;
            *(float2*)&g_y[(size_t)r1 * 128 + col] = v;
        }
        if (r2 < N_NODES) {
            float2 v;
            v.x = acc[nt][2] + b0v;
            v.y = acc[nt][3] + b1v;
            *(float2*)&g_y[(size_t)r2 * 128 + col] = v;
        }
    }
}

// ---------------- BN1 raw stats over y ----------------
__global__ void bn1_stats_k(int layer) {
    __shared__ float rs[2048];
    int tid = threadIdx.x, lane = tid & 31, warp = tid >> 5;
    int c0 = lane * 4;
    float4 s = make_float4(0.f, 0.f, 0.f, 0.f);
    float4 q = make_float4(0.f, 0.f, 0.f, 0.f);
    const float4* y4 = (const float4*)g_y;
    int n4 = ND / 4;
    for (int i = blockIdx.x * 256 + tid; i < n4; i += gridDim.x * 256) {
        float4 v = y4[i];
        s.x += v.x; s.y += v.y; s.z += v.z; s.w += v.w;
        q.x += v.x * v.x; q.y += v.y * v.y; q.z += v.z * v.z; q.w += v.w * v.w;
    }
    rs[warp * 128 + c0 + 0] = s.x; rs[warp * 128 + c0 + 1] = s.y;
    rs[warp * 128 + c0 + 2] = s.z; rs[warp * 128 + c0 + 3] = s.w;
    rs[1024 + warp * 128 + c0 + 0] = q.x; rs[1024 + warp * 128 + c0 + 1] = q.y;
    rs[1024 + warp * 128 + c0 + 2] = q.z; rs[1024 + warp * 128 + c0 + 3] = q.w;
    __syncthreads();
    int col = tid & 127;
    int so = (tid >> 7) * 1024;
    float v = 0.f;
    #pragma unroll
    for (int w = 0; w < 8; w++) v += rs[so + w * 128 + col];
    atomicAdd(&g_sA[layer][(tid >> 7) * 128 + col], v);
}

// read-only on g_y: apply BN1+ReLU on the fly, accumulate BN2 stats
__global__ void bn_relu_stats_k(const float* __restrict__ gamma1, const float* __restrict__ beta1,
                                int layer) {
    __shared__ float rs[2048];
    int tid = threadIdx.x, lane = tid & 31, warp = tid >> 5;
    int c0 = lane * 4;
    float4 sc, sh;
    bn_consts(g_sA[layer], gamma1, beta1, c0, sc, sh);
    float4 s = make_float4(0.f, 0.f, 0.f, 0.f);
    float4 q = make_float4(0.f, 0.f, 0.f, 0.f);
    const float4* y4 = (const float4*)g_y;
    int n4 = ND / 4;
    for (int i = blockIdx.x * 256 + tid; i < n4; i += gridDim.x * 256) {
        float4 v = y4[i];
        v.x = fmaxf(fmaf(v.x, sc.x, sh.x), 0.f);
        v.y = fmaxf(fmaf(v.y, sc.y, sh.y), 0.f);
        v.z = fmaxf(fmaf(v.z, sc.z, sh.z), 0.f);
        v.w = fmaxf(fmaf(v.w, sc.w, sh.w), 0.f);
        s.x += v.x; s.y += v.y; s.z += v.z; s.w += v.w;
        q.x += v.x * v.x; q.y += v.y * v.y; q.z += v.z * v.z; q.w += v.w * v.w;
    }
    rs[warp * 128 + c0 + 0] = s.x; rs[warp * 128 + c0 + 1] = s.y;
    rs[warp * 128 + c0 + 2] = s.z; rs[warp * 128 + c0 + 3] = s.w;
    rs[1024 + warp * 128 + c0 + 0] = q.x; rs[1024 + warp * 128 + c0 + 1] = q.y;
    rs[1024 + warp * 128 + c0 + 2] = q.z; rs[1024 + warp * 128 + c0 + 3] = q.w;
    __syncthreads();
    int col = tid & 127;
    int so = (tid >> 7) * 1024;
    float v = 0.f;
    #pragma unroll
    for (int w = 0; w < 8; w++) v += rs[so + w * 128 + col];
    atomicAdd(&g_sB[layer][(tid >> 7) * 128 + col], v);
}

// out = relu(bn2(relu(bn1(y)))) -> fp32 slab + fp16 mirror
__global__ void bn_relu_out_k(float* __restrict__ out,
                              const float* __restrict__ gamma1, const float* __restrict__ beta1,
                              const float* __restrict__ gamma2, const float* __restrict__ beta2,
                              int layer) {
    int tid = threadIdx.x, lane = tid & 31;
    int c0 = lane * 4;
    float4 sc1, sh1, sc2, sh2;
    bn_consts(g_sA[layer], gamma1, beta1, c0, sc1, sh1);
    bn_consts(g_sB[layer], gamma2, beta2, c0, sc2, sh2);
    const float4* y4 = (const float4*)g_y;
    float4* o4 = (float4*)out;
    uint2* h16 = (uint2*)g_h16;
    int n4 = ND / 4;
    for (int i = blockIdx.x * 256 + tid; i < n4; i += gridDim.x * 256) {
        float4 v = y4[i];
        v.x = fmaxf(fmaf(v.x, sc1.x, sh1.x), 0.f);
        v.y = fmaxf(fmaf(v.y, sc1.y, sh1.y), 0.f);
        v.z = fmaxf(fmaf(v.z, sc1.z, sh1.z), 0.f);
        v.w = fmaxf(fmaf(v.w, sc1.w, sh1.w), 0.f);
        v.x = fmaxf(fmaf(v.x, sc2.x, sh2.x), 0.f);
        v.y = fmaxf(fmaf(v.y, sc2.y, sh2.y), 0.f);
        v.z = fmaxf(fmaf(v.z, sc2.z, sh2.z), 0.f);
        v.w = fmaxf(fmaf(v.w, sc2.w, sh2.w), 0.f);
        o4[i] = v;
        h16[i] = pack16(v);
    }
}

extern "C" void kernel_launch(void* const* d_in, const int* in_sizes, int n_in,
                              void* d_out, int out_size) {
    const float* features = (const float*)d_in[0];
    const float* W   = (const float*)d_in[1];
    const float* b   = (const float*)d_in[2];
    const float* eps = (const float*)d_in[3];
    const float* g1  = (const float*)d_in[4];
    const float* be1 = (const float*)d_in[5];
    const float* g2  = (const float*)d_in[6];
    const float* be2 = (const float*)d_in[7];
    const int* src   = (const int*)d_in[8];
    const int* dst   = (const int*)d_in[9];
    int nE = in_sizes[8];
    float* out = (float*)d_out;

    static bool once = []() {
        cudaFuncSetAttribute(gemm_mma_k, cudaFuncAttributeMaxDynamicSharedMemorySize,
                             MMA_SMEM_BYTES);
        return true;
    }();
    (void)once;

    copyzero_k<<<1184, 256>>>(out, features, W);
    hist_k<<<6250, 256>>>(dst, nE);
    scan_k<<<1, 1024>>>(nE);
    fill_k<<<6250, 256>>>(src, dst, nE);

    for (int i = 0; i < 3; i++) {
        const float* h = out + (size_t)i * ND;
        float* hn = out + (size_t)(i + 1) * ND;
        gather_k<<<1250, 256>>>(h, eps, i);
        gemm_mma_k<<<NTILE, 256, MMA_SMEM_BYTES>>>(b + (size_t)i * D, i);
        bn1_stats_k<<<1184, 256>>>(i);
        bn_relu_stats_k<<<1184, 256>>>(g1 + i * D, be1 + i * D, i);
        bn_relu_out_k<<<1184, 256>>>(hn, g1 + i * D, be1 + i * D, g2 + i * D, be2 + i * D, i);
    }
}